// round 9
// baseline (speedup 1.0000x reference)
#include <cuda_runtime.h>
#include <cuda_bf16.h>

#define BATCH_   8192
#define EMB_     1024
#define ENT_DIM_ 64
#define G_       16
#define N_REL_   5000
#define LN_EPS_  1e-5f
#define NT_      256
#define TSTRIDE_ 1025               // padded row stride (floats) for T[j][o]
#define SMEM_BYTES_ ((16 * TSTRIDE_ + EMB_ + 16) * 4)

// scratch (allocation-free per harness rules)
__device__ int d_hist[N_REL_];
__device__ int d_start[N_REL_];
__device__ int d_offs[N_REL_];
__device__ int d_perm[BATCH_];

__global__ void zero_kernel() {
    int i = blockIdx.x * blockDim.x + threadIdx.x;
    if (i < N_REL_) d_hist[i] = 0;
}

__global__ void hist_kernel(const int* __restrict__ ids) {
    int i = blockIdx.x * blockDim.x + threadIdx.x;
    if (i < BATCH_) {
        int r = ids[i];
        r = (r < 0) ? 0 : (r >= N_REL_ ? N_REL_ - 1 : r);
        atomicAdd(&d_hist[r], 1);
    }
}

// single-block exclusive scan of d_hist -> d_start (pristine) and d_offs (cursor)
__global__ __launch_bounds__(1024) void scan_kernel() {
    __shared__ int wsum[32];
    __shared__ int carry_sh;
    __shared__ int ttotal;
    const int tid = threadIdx.x, lane = tid & 31, wid = tid >> 5;
    if (tid == 0) carry_sh = 0;
    __syncthreads();
    for (int base = 0; base < N_REL_; base += 1024) {
        int i = base + tid;
        int v = (i < N_REL_) ? d_hist[i] : 0;
        int x = v;
        #pragma unroll
        for (int off = 1; off < 32; off <<= 1) {
            int y = __shfl_up_sync(0xffffffffu, x, off);
            if (lane >= off) x += y;
        }
        if (lane == 31) wsum[wid] = x;
        __syncthreads();
        if (wid == 0) {
            int w = wsum[lane];
            int xs = w;
            #pragma unroll
            for (int off = 1; off < 32; off <<= 1) {
                int y = __shfl_up_sync(0xffffffffu, xs, off);
                if (lane >= off) xs += y;
            }
            if (lane == 31) ttotal = xs;
            wsum[lane] = xs - w;   // exclusive warp prefix
        }
        __syncthreads();
        int excl = carry_sh + wsum[wid] + (x - v);
        if (i < N_REL_) { d_start[i] = excl; d_offs[i] = excl; }
        __syncthreads();
        if (tid == 0) carry_sh += ttotal;
        __syncthreads();
    }
}

__global__ void scatter_kernel(const int* __restrict__ ids) {
    int i = blockIdx.x * blockDim.x + threadIdx.x;
    if (i < BATCH_) {
        int r = ids[i];
        r = (r < 0) ? 0 : (r >= N_REL_ ? N_REL_ - 1 : r);
        int pos = atomicAdd(&d_offs[r], 1);
        d_perm[pos] = i;
    }
}

// One CTA per relation id. Loads the 64KB tran tile once into SMEM
// (transposed, padded), then loops over all batch rows with this id.
__global__ __launch_bounds__(NT_) void wproj_group_kernel(
    const float* __restrict__ ent,
    const float* __restrict__ tran,
    const float* __restrict__ bias,
    const float* __restrict__ lnw,
    const float* __restrict__ lnb,
    float* __restrict__ out)
{
    extern __shared__ float sm[];
    float* T    = sm;                      // [16][TSTRIDE_]
    float* e_sm = sm + 16 * TSTRIDE_;      // [1024]
    float* red  = e_sm + EMB_;             // [16]

    const int g   = blockIdx.x;
    const int cnt = d_hist[g];
    if (cnt == 0) return;
    const int start = d_start[g];
    const int tid   = threadIdx.x;

    // ---- load tran tile (1024 x 16 floats) transposed into SMEM ----
    {
        const float4* t4 = reinterpret_cast<const float4*>(tran + (size_t)g * (ENT_DIM_ * G_ * G_));
        #pragma unroll
        for (int it = 0; it < 16; it++) {
            int f = tid + it * NT_;          // float4 index 0..4095
            int o  = f >> 2;                 // output index
            int jb = (f & 3) * 4;            // j base
            float4 v = t4[f];
            T[(jb + 0) * TSTRIDE_ + o] = v.x;
            T[(jb + 1) * TSTRIDE_ + o] = v.y;
            T[(jb + 2) * TSTRIDE_ + o] = v.z;
            T[(jb + 3) * TSTRIDE_ + o] = v.w;
        }
    }

    // ---- hoist per-group / per-o constants into registers ----
    float bv[4], lw[4], lb[4];
    {
        const float* bbase = bias + (size_t)g * EMB_;
        #pragma unroll
        for (int k = 0; k < 4; k++) {
            int o = tid + k * NT_;
            bv[k] = __ldg(bbase + o);
            lw[k] = __ldg(lnw + o);
            lb[k] = __ldg(lnb + o);
        }
    }
    __syncthreads();

    const int wid  = tid >> 5;
    const int lane = tid & 31;
    const float inv_n = 1.f / (float)EMB_;

    for (int i = 0; i < cnt; i++) {
        const int row = d_perm[start + i];

        // stage entity row
        {
            float4 ev = reinterpret_cast<const float4*>(ent + (size_t)row * EMB_)[tid];
            reinterpret_cast<float4*>(e_sm)[tid] = ev;
        }
        __syncthreads();

        float x[4];
        float s = 0.f, s2 = 0.f;
        #pragma unroll
        for (int k = 0; k < 4; k++) {
            const int o = tid + k * NT_;
            const float* ep = e_sm + (o >> 4) * G_;
            float acc = bv[k];
            #pragma unroll
            for (int j = 0; j < 16; j++)
                acc += T[j * TSTRIDE_ + o] * ep[j];
            x[k] = acc;
            s  += acc;
            s2 += acc * acc;
        }

        #pragma unroll
        for (int off = 16; off > 0; off >>= 1) {
            s  += __shfl_xor_sync(0xffffffffu, s,  off);
            s2 += __shfl_xor_sync(0xffffffffu, s2, off);
        }
        if (lane == 0) { red[wid] = s; red[8 + wid] = s2; }
        __syncthreads();
        if (wid == 0) {
            float a  = (lane < 8) ? red[lane]     : 0.f;
            float a2 = (lane < 8) ? red[8 + lane] : 0.f;
            #pragma unroll
            for (int off = 4; off > 0; off >>= 1) {
                a  += __shfl_xor_sync(0xffffffffu, a,  off);
                a2 += __shfl_xor_sync(0xffffffffu, a2, off);
            }
            if (lane == 0) { red[0] = a; red[1] = a2; }
        }
        __syncthreads();

        const float mu   = red[0] * inv_n;
        const float var  = red[1] * inv_n - mu * mu;
        const float rstd = rsqrtf(var + LN_EPS_);

        float* orow = out + (size_t)row * EMB_;
        #pragma unroll
        for (int k = 0; k < 4; k++) {
            const int o = tid + k * NT_;
            orow[o] = (x[k] - mu) * rstd * lw[k] + lb[k];
        }
        __syncthreads();   // red/e_sm reuse guard for next row
    }
}

extern "C" void kernel_launch(void* const* d_in, const int* in_sizes, int n_in,
                              void* d_out, int out_size) {
    const float* ent  = (const float*)d_in[0];
    const int*   ids  = (const int*)d_in[1];
    const float* tran = (const float*)d_in[2];
    const float* bias = (const float*)d_in[3];
    const float* lnw  = (const float*)d_in[4];
    const float* lnb  = (const float*)d_in[5];
    float* out = (float*)d_out;

    cudaFuncSetAttribute(wproj_group_kernel,
                         cudaFuncAttributeMaxDynamicSharedMemorySize, SMEM_BYTES_);

    zero_kernel<<<(N_REL_ + 255) / 256, 256>>>();
    hist_kernel<<<(BATCH_ + 255) / 256, 256>>>(ids);
    scan_kernel<<<1, 1024>>>();
    scatter_kernel<<<(BATCH_ + 255) / 256, 256>>>(ids);
    wproj_group_kernel<<<N_REL_, NT_, SMEM_BYTES_>>>(ent, tran, bias, lnw, lnb, out);
}

// round 14
// speedup vs baseline: 1.0873x; 1.0873x over previous
#include <cuda_runtime.h>
#include <cuda_bf16.h>
#include <cstdint>

#define BATCH_   8192
#define EMB_     1024
#define ENT_DIM_ 64
#define G_       16
#define N_REL_   5000
#define LN_EPS_  1e-5f
#define NT_      256
#define TSTRIDE_ 1025               // padded row stride (floats) for T[j][o]
#define SMEM_BYTES_ ((16 * TSTRIDE_ + 2 * EMB_ + 16) * 4)

// scratch (allocation-free per harness rules)
__device__ int d_hist[N_REL_];
__device__ int d_start[N_REL_];
__device__ int d_perm[BATCH_];

__device__ __forceinline__ void cp_async16(void* smem_dst, const void* gptr) {
    uint32_t sa = (uint32_t)__cvta_generic_to_shared(smem_dst);
    asm volatile("cp.async.cg.shared.global [%0], [%1], 16;\n" :: "r"(sa), "l"(gptr));
}
__device__ __forceinline__ void cp_async_commit() {
    asm volatile("cp.async.commit_group;\n");
}
__device__ __forceinline__ void cp_async_wait_all() {
    asm volatile("cp.async.wait_group 0;\n");
}

// ---- fused prepass: hist + exclusive scan + scatter, one CTA ----
__global__ __launch_bounds__(1024) void prep_kernel(const int* __restrict__ ids) {
    __shared__ int h[N_REL_];
    __shared__ int c[N_REL_];
    __shared__ int wsum[32];
    __shared__ int carry_sh, ttotal;
    const int tid = threadIdx.x, lane = tid & 31, wid = tid >> 5;

    for (int i = tid; i < N_REL_; i += 1024) h[i] = 0;
    if (tid == 0) carry_sh = 0;
    __syncthreads();

    for (int i = tid; i < BATCH_; i += 1024) {
        int r = ids[i];
        r = (r < 0) ? 0 : (r >= N_REL_ ? N_REL_ - 1 : r);
        atomicAdd(&h[r], 1);
    }
    __syncthreads();

    // exclusive scan h -> c (cursor) and d_start, export d_hist
    for (int base = 0; base < N_REL_; base += 1024) {
        int i = base + tid;
        int v = (i < N_REL_) ? h[i] : 0;
        int x = v;
        #pragma unroll
        for (int off = 1; off < 32; off <<= 1) {
            int y = __shfl_up_sync(0xffffffffu, x, off);
            if (lane >= off) x += y;
        }
        if (lane == 31) wsum[wid] = x;
        __syncthreads();
        if (wid == 0) {
            int w = wsum[lane];
            int xs = w;
            #pragma unroll
            for (int off = 1; off < 32; off <<= 1) {
                int y = __shfl_up_sync(0xffffffffu, xs, off);
                if (lane >= off) xs += y;
            }
            if (lane == 31) ttotal = xs;
            wsum[lane] = xs - w;
        }
        __syncthreads();
        int excl = carry_sh + wsum[wid] + (x - v);
        if (i < N_REL_) { c[i] = excl; d_start[i] = excl; d_hist[i] = v; }
        __syncthreads();
        if (tid == 0) carry_sh += ttotal;
        __syncthreads();
    }

    for (int i = tid; i < BATCH_; i += 1024) {
        int r = ids[i];
        r = (r < 0) ? 0 : (r >= N_REL_ ? N_REL_ - 1 : r);
        int pos = atomicAdd(&c[r], 1);
        d_perm[pos] = i;
    }
}

// One CTA per relation id: tile in SMEM once, cp.async-pipelined rows.
__global__ __launch_bounds__(NT_) void wproj_group_kernel(
    const float* __restrict__ ent,
    const float* __restrict__ tran,
    const float* __restrict__ bias,
    const float* __restrict__ lnw,
    const float* __restrict__ lnb,
    float* __restrict__ out)
{
    extern __shared__ float sm[];
    float* T  = sm;                       // [16][TSTRIDE_]
    float* e2 = sm + 16 * TSTRIDE_;       // [2][1024] double buffer
    float* red = e2 + 2 * EMB_;           // [16]

    const int g   = blockIdx.x;
    const int cnt = d_hist[g];
    if (cnt == 0) return;
    const int start = d_start[g];
    const int tid   = threadIdx.x;

    // prefetch row 0's ent slice first (overlaps tile fill DRAM)
    int cur_row = d_perm[start];
    cp_async16(e2 + tid * 4, ent + (size_t)cur_row * EMB_ + tid * 4);
    cp_async_commit();

    // ---- tile fill: 1024x16 floats, transposed into T ----
    {
        const float4* t4 = reinterpret_cast<const float4*>(tran + (size_t)g * (ENT_DIM_ * G_ * G_));
        #pragma unroll
        for (int it = 0; it < 16; it++) {
            int f  = tid + it * NT_;
            int o  = f >> 2;
            int jb = (f & 3) * 4;
            float4 v = t4[f];
            T[(jb + 0) * TSTRIDE_ + o] = v.x;
            T[(jb + 1) * TSTRIDE_ + o] = v.y;
            T[(jb + 2) * TSTRIDE_ + o] = v.z;
            T[(jb + 3) * TSTRIDE_ + o] = v.w;
        }
    }

    float bv[4], lw[4], lb[4];
    {
        const float* bbase = bias + (size_t)g * EMB_;
        #pragma unroll
        for (int k = 0; k < 4; k++) {
            int o = tid + k * NT_;
            bv[k] = __ldg(bbase + o);
            lw[k] = __ldg(lnw + o);
            lb[k] = __ldg(lnb + o);
        }
    }
    cp_async_wait_all();
    __syncthreads();

    const int wid  = tid >> 5;
    const int lane = tid & 31;
    const float inv_n = 1.f / (float)EMB_;

    for (int i = 0; i < cnt; i++) {
        const float* ebuf = e2 + (i & 1) * EMB_;
        int next_row = -1;
        if (i + 1 < cnt) {
            next_row = d_perm[start + i + 1];
            cp_async16(e2 + ((i + 1) & 1) * EMB_ + tid * 4,
                       ent + (size_t)next_row * EMB_ + tid * 4);
            cp_async_commit();
        }

        float x[4];
        float s = 0.f, s2 = 0.f;
        #pragma unroll
        for (int k = 0; k < 4; k++) {
            const int o = tid + k * NT_;
            const float* ep = ebuf + (o >> 4) * G_;
            float acc = bv[k];
            #pragma unroll
            for (int j = 0; j < 16; j++)
                acc += T[j * TSTRIDE_ + o] * ep[j];
            x[k] = acc;
            s  += acc;
            s2 += acc * acc;
        }

        #pragma unroll
        for (int off = 16; off > 0; off >>= 1) {
            s  += __shfl_xor_sync(0xffffffffu, s,  off);
            s2 += __shfl_xor_sync(0xffffffffu, s2, off);
        }
        if (lane == 0) { red[wid] = s; red[8 + wid] = s2; }
        __syncthreads();
        float S = 0.f, S2 = 0.f;
        #pragma unroll
        for (int w = 0; w < 8; w++) { S += red[w]; S2 += red[8 + w]; }

        const float mu   = S * inv_n;
        const float var  = S2 * inv_n - mu * mu;
        const float rstd = rsqrtf(var + LN_EPS_);

        float* orow = out + (size_t)cur_row * EMB_;
        #pragma unroll
        for (int k = 0; k < 4; k++) {
            const int o = tid + k * NT_;
            orow[o] = (x[k] - mu) * rstd * lw[k] + lb[k];
        }

        cur_row = next_row;
        cp_async_wait_all();
        __syncthreads();   // red reuse + e buffer visibility for next iter
    }
}

extern "C" void kernel_launch(void* const* d_in, const int* in_sizes, int n_in,
                              void* d_out, int out_size) {
    const float* ent  = (const float*)d_in[0];
    const int*   ids  = (const int*)d_in[1];
    const float* tran = (const float*)d_in[2];
    const float* bias = (const float*)d_in[3];
    const float* lnw  = (const float*)d_in[4];
    const float* lnb  = (const float*)d_in[5];
    float* out = (float*)d_out;

    cudaFuncSetAttribute(wproj_group_kernel,
                         cudaFuncAttributeMaxDynamicSharedMemorySize, SMEM_BYTES_);

    prep_kernel<<<1, 1024>>>(ids);
    wproj_group_kernel<<<N_REL_, NT_, SMEM_BYTES_>>>(ent, tran, bias, lnw, lnb, out);
}